// round 10
// baseline (speedup 1.0000x reference)
#include <cuda_runtime.h>
#include <cuda_fp16.h>
#include <cstdint>

// LinearSelfAttention, fp16 mma.sync + ldmatrix, 256+1 border decomposition.
// out[d][t] = H[d][t] + sum_e W[d][e] H[e][t] / n,  W = P G Q - u v^T,
// G = H H^T, u = P h_n, v = Q^T h_n.
// Core GEMMs run on the 256/2048 interior; the +1 borders are rank-1 terms
// and GEMV kernels computed in fp32.

#define RDIM 257
#define NCOL 2049
#define NBAT 16
#define INV_N (1.0f / 2048.0f)

#define DC 256       // core d extent
#define TC 2048      // core t extent
#define LDS_ 384     // small-stage padded ld
#define GB_  ((size_t)LDS_ * LDS_)
#define HB   ((size_t)RDIM * NCOL)
#define HCB  ((size_t)DC * TC)

__device__ __half g_Hc[NBAT][DC * TC];     // H core, K-major over t
__device__ __half g_Htc[NBAT][TC * DC];    // H^T core, K-major over d
__device__ __half g_Pp[LDS_ * LDS_];       // padded P
__device__ __half g_Qt[LDS_ * LDS_];       // padded Q^T
__device__ float  g_Gp[3][NBAT][DC * DC];  // syrk split-K partials
__device__ __half g_G[NBAT][LDS_ * LDS_];  // padded G (pads stay 0)
__device__ __half g_Tt[NBAT][LDS_ * LDS_]; // (G Q)^T
__device__ __half g_W[NBAT][LDS_ * LDS_];
__device__ float  g_u[NBAT][LDS_];         // pads stay 0
__device__ float  g_v[NBAT][LDS_];
__device__ float  g_hc[NBAT][RDIM];        // H[:, 2048]
__device__ float  g_wcol[NBAT][LDS_];      // W[:, 256]

// ---------------------------------------------------------------------------
__device__ __forceinline__ uint32_t smem_u32(const void* p) {
    uint32_t a;
    asm("{ .reg .u64 t; cvta.to.shared.u64 t, %1; cvt.u32.u64 %0, t; }"
        : "=r"(a) : "l"(p));
    return a;
}
__device__ __forceinline__ void cp16a(uint32_t sa, const void* g) {
    asm volatile("cp.async.cg.shared.global [%0], [%1], 16;"
                 :: "r"(sa), "l"(g) : "memory");
}
#define CP_COMMIT() asm volatile("cp.async.commit_group;" ::: "memory")
#define CP_WAITN(n) asm volatile("cp.async.wait_group %0;" :: "n"(n) : "memory")

__device__ __forceinline__ void mma8(float* c, const uint32_t* a,
                                     const uint32_t* b) {
    asm volatile(
        "mma.sync.aligned.m16n8k16.row.col.f32.f16.f16.f32 "
        "{%0,%1,%2,%3}, {%4,%5,%6,%7}, {%8,%9}, {%0,%1,%2,%3};"
        : "+f"(c[0]), "+f"(c[1]), "+f"(c[2]), "+f"(c[3])
        : "r"(a[0]), "r"(a[1]), "r"(a[2]), "r"(a[3]), "r"(b[0]), "r"(b[1]));
}
__device__ __forceinline__ void ldsm4(uint32_t* r, uint32_t a) {
    asm volatile(
        "ldmatrix.sync.aligned.m8n8.x4.shared.b16 {%0,%1,%2,%3}, [%4];"
        : "=r"(r[0]), "=r"(r[1]), "=r"(r[2]), "=r"(r[3]) : "r"(a));
}

// Swizzled tile load: 128 rows x 64 halfs (128 B/row), chunk c at (c^(r&7)).
#define TILE_B 16384
#define SMEM_GEMM (6 * TILE_B)

__device__ __forceinline__ void loadS(uint32_t sbase, const __half* __restrict__ g,
                                      int ld, int r0, int k0, int tid) {
    const int chunk = tid & 7;
    const int rb = tid >> 3;
    const __half* gp = g + (size_t)r0 * ld + k0 + chunk * 8;
#pragma unroll
    for (int i = 0; i < 4; i++) {
        const int r = rb + i * 32;
        const uint32_t off = (uint32_t)(r * 128 + ((chunk ^ (r & 7)) << 4));
        cp16a(sbase + off, gp + (size_t)r * ld);
    }
}

__device__ __forceinline__ void chunk_mma(uint32_t Ab, uint32_t Bb, int lane,
                                          int wm, int wn, float (&acc)[2][8][4]) {
    const int rA = lane & 15;
    const int hi = lane >> 4;
#pragma unroll
    for (int ks = 0; ks < 4; ks++) {
        uint32_t a[2][4], bt[4][4];
#pragma unroll
        for (int mt = 0; mt < 2; mt++) {
            const int row = wm + mt * 16 + rA;
            ldsm4(a[mt], Ab + row * 128 + (((ks * 2 + hi) ^ (row & 7)) << 4));
        }
#pragma unroll
        for (int n2 = 0; n2 < 4; n2++) {
            const int row = wn + n2 * 16 + rA;
            ldsm4(bt[n2], Bb + row * 128 + (((ks * 2 + hi) ^ (row & 7)) << 4));
        }
#pragma unroll
        for (int mt = 0; mt < 2; mt++)
#pragma unroll
            for (int n2 = 0; n2 < 4; n2++) {
                uint32_t b0[2] = {bt[n2][0], bt[n2][2]};
                uint32_t b1[2] = {bt[n2][1], bt[n2][3]};
                mma8(acc[mt][2 * n2 + 0], a[mt], b0);
                mma8(acc[mt][2 * n2 + 1], a[mt], b1);
            }
    }
}

#define DECL_FRAG() \
    float acc[2][8][4]; \
    _Pragma("unroll") for (int i = 0; i < 2; i++) \
    _Pragma("unroll") for (int j = 0; j < 8; j++) \
    _Pragma("unroll") for (int r = 0; r < 4; r++) acc[i][j][r] = 0.0f;

// ---------------------------------------------------------------------------
// syrk core: Gp[sp] = Hc (x) Hc over K chunk range. 3 sym tiles, split-K x3.
// grid (3,1,48), 96KB smem.
// ---------------------------------------------------------------------------
__global__ void __launch_bounds__(256, 2) k_syrk() {
    extern __shared__ __half sm[];
    const uint32_t sbase = smem_u32(sm);
    const int tid = threadIdx.x;
    const int b = blockIdx.z / 3;
    const int sp = blockIdx.z % 3;
    const int TI[3] = {0, 0, 1};
    const int TJ[3] = {0, 1, 1};
    const int ti = TI[blockIdx.x], tj = TJ[blockIdx.x];
    const int m0 = ti * 128, n0 = tj * 128;
    const int c0 = sp * 11;
    const int nc = (sp == 2) ? 10 : 11;

    const __half* Hb = g_Hc[b];
    float* Cf = &g_Gp[sp][b][0];

    const int lane = tid & 31, wid = tid >> 5;
    const int wm = (wid & 3) * 32;
    const int wn = (wid >> 2) * 64;
    const int g = lane >> 2, tg = lane & 3;

    DECL_FRAG();

#pragma unroll
    for (int c = 0; c < 2; c++) {
        loadS(sbase + c * TILE_B, Hb, TC, m0, (c0 + c) * 64, tid);
        loadS(sbase + (3 + c) * TILE_B, Hb, TC, n0, (c0 + c) * 64, tid);
        CP_COMMIT();
    }
    for (int c = 0; c < nc; c++) {
        if (c + 2 < nc) {
            const int nb = (c + 2) % 3;
            const int k0 = (c0 + c + 2) * 64;
            loadS(sbase + nb * TILE_B, Hb, TC, m0, k0, tid);
            loadS(sbase + (3 + nb) * TILE_B, Hb, TC, n0, k0, tid);
        }
        CP_COMMIT();
        CP_WAITN(2);
        __syncthreads();
        chunk_mma(sbase + (c % 3) * TILE_B, sbase + (3 + c % 3) * TILE_B,
                  lane, wm, wn, acc);
        __syncthreads();
    }

#pragma unroll
    for (int mt = 0; mt < 2; mt++) {
#pragma unroll
        for (int half = 0; half < 2; half++) {
            const int row = m0 + wm + mt * 16 + g + half * 8;
#pragma unroll
            for (int nt = 0; nt < 8; nt++) {
                const int col = n0 + wn + nt * 8 + tg * 2;
                const float v0 = acc[mt][nt][half * 2 + 0];
                const float v1 = acc[mt][nt][half * 2 + 1];
                float2 st = {v0, v1};
                *(float2*)&Cf[(size_t)row * DC + col] = st;
                if (ti != tj) {
                    Cf[(size_t)col * DC + row] = v0;
                    Cf[(size_t)(col + 1) * DC + row] = v1;
                }
            }
        }
    }
}

// ---------------------------------------------------------------------------
// gred: G[r][c] (core) = p0+p1+p2 + hc[r]*hc[c] -> fp16 padded (ld 384)
// grid (64,16), block 256.
// ---------------------------------------------------------------------------
__global__ void k_gred() {
    const int b = blockIdx.y;
    const int i = (blockIdx.x * 256 + threadIdx.x) * 4;
    const int r = i >> 8, c = i & 255;
    float4 x = *(const float4*)&g_Gp[0][b][i];
    float4 y = *(const float4*)&g_Gp[1][b][i];
    float4 z = *(const float4*)&g_Gp[2][b][i];
    const float hr = g_hc[b][r];
    const float* hcb = g_hc[b];
    float v0 = x.x + y.x + z.x + hr * hcb[c + 0];
    float v1 = x.y + y.y + z.y + hr * hcb[c + 1];
    float v2 = x.z + y.z + z.z + hr * hcb[c + 2];
    float v3 = x.w + y.w + z.w + hr * hcb[c + 3];
    __half* o = &g_G[b][(size_t)r * LDS_ + c];
    *(__half2*)(o + 0) = __floats2half2_rn(v0, v1);
    *(__half2*)(o + 2) = __floats2half2_rn(v2, v3);
}

// ---------------------------------------------------------------------------
// gb: G border row/col 256: G[256][d] = dot(H[256,:], H[d,:]) over 2049, fp32.
// grid (33,16), block 256 (8 warps, warp = one d).
// ---------------------------------------------------------------------------
__global__ void k_gb(const float* __restrict__ H) {
    const int b = blockIdx.y;
    const int d = blockIdx.x * 8 + (threadIdx.x >> 5);
    if (d > 256) return;
    const int lane = threadIdx.x & 31;
    const float* Hb = H + (size_t)b * HB;
    const float* ra = Hb + (size_t)256 * NCOL;
    const float* rd = Hb + (size_t)d * NCOL;
    float s = 0.0f;
    for (int t = lane; t < NCOL; t += 32) s = fmaf(ra[t], rd[t], s);
#pragma unroll
    for (int o = 16; o > 0; o >>= 1) s += __shfl_xor_sync(0xFFFFFFFF, s, o);
    if (lane == 0) {
        const __half h = __float2half_rn(s);
        g_G[b][(size_t)256 * LDS_ + d] = h;
        g_G[b][(size_t)d * LDS_ + 256] = h;
    }
}

// ---------------------------------------------------------------------------
// small stages, padded 384, K=320 (5 chunks):
//  MODE 1: T' = Qt (x) G
//  MODE 2: W  = Pp (x) T' - u v^T   (+ extract wcol = W[:,256])
// grid (3,3,16), 96KB smem.
// ---------------------------------------------------------------------------
template <int MODE>
__global__ void __launch_bounds__(256, 2)
k_ld(const __half* __restrict__ A, size_t sA,
     const __half* __restrict__ B, size_t sB,
     __half* __restrict__ C, size_t sC) {
    extern __shared__ __half sm[];
    const uint32_t sbase = smem_u32(sm);
    const int tid = threadIdx.x;
    const int b = blockIdx.z;
    const int m0 = blockIdx.y * 128, n0 = blockIdx.x * 128;
    const __half* Ab = A + (size_t)b * sA;
    const __half* Bb = B + (size_t)b * sB;
    __half* Cb = C + (size_t)b * sC;

    const int lane = tid & 31, wid = tid >> 5;
    const int wm = (wid & 3) * 32;
    const int wn = (wid >> 2) * 64;
    const int g = lane >> 2, tg = lane & 3;

    DECL_FRAG();

#pragma unroll
    for (int c = 0; c < 2; c++) {
        loadS(sbase + c * TILE_B, Ab, LDS_, m0, c * 64, tid);
        loadS(sbase + (3 + c) * TILE_B, Bb, LDS_, n0, c * 64, tid);
        CP_COMMIT();
    }
#pragma unroll
    for (int c = 0; c < 5; c++) {
        if (c + 2 < 5) {
            const int nb = (c + 2) % 3;
            loadS(sbase + nb * TILE_B, Ab, LDS_, m0, (c + 2) * 64, tid);
            loadS(sbase + (3 + nb) * TILE_B, Bb, LDS_, n0, (c + 2) * 64, tid);
        }
        CP_COMMIT();
        CP_WAITN(2);
        __syncthreads();
        chunk_mma(sbase + (c % 3) * TILE_B, sbase + (3 + c % 3) * TILE_B,
                  lane, wm, wn, acc);
        __syncthreads();
    }

#pragma unroll
    for (int mt = 0; mt < 2; mt++) {
#pragma unroll
        for (int half = 0; half < 2; half++) {
            const int row = m0 + wm + mt * 16 + g + half * 8;
            float uu = 0.0f;
            if (MODE == 2) uu = g_u[b][row];
#pragma unroll
            for (int nt = 0; nt < 8; nt++) {
                const int col = n0 + wn + nt * 8 + tg * 2;
                float v0 = acc[mt][nt][half * 2 + 0];
                float v1 = acc[mt][nt][half * 2 + 1];
                if (MODE == 2) {
                    v0 -= uu * g_v[b][col];
                    v1 -= uu * g_v[b][col + 1];
                    if (col == 256) g_wcol[b][row] = v0;
                }
                *(__half2*)&Cb[(size_t)row * LDS_ + col] =
                    __floats2half2_rn(v0, v1);
            }
        }
    }
}

// ---------------------------------------------------------------------------
// out core: d<256, t<2048, e<256 GEMM + rank-1 wcol[d]*H[256][t].
// grid (16,2,16), 96KB smem, K=256 (4 chunks).
// ---------------------------------------------------------------------------
__global__ void __launch_bounds__(256, 2)
k_outc(const float* __restrict__ H, float* __restrict__ out) {
    extern __shared__ __half sm[];
    const uint32_t sbase = smem_u32(sm);
    const int tid = threadIdx.x;
    const int b = blockIdx.z;
    const int n0 = blockIdx.x * 128;   // t
    const int m0 = blockIdx.y * 128;   // d
    const __half* Ab = g_W[b];         // ld 384
    const __half* Bb = g_Htc[b];       // ld 256
    const float* Hb = H + (size_t)b * HB;
    float* Ob = out + (size_t)b * HB;
    const float* hrow = Hb + (size_t)256 * NCOL;

    const int lane = tid & 31, wid = tid >> 5;
    const int wm = (wid & 3) * 32;
    const int wn = (wid >> 2) * 64;
    const int g = lane >> 2, tg = lane & 3;

    DECL_FRAG();

#pragma unroll
    for (int c = 0; c < 2; c++) {
        loadS(sbase + c * TILE_B, Ab, LDS_, m0, c * 64, tid);
        loadS(sbase + (3 + c) * TILE_B, Bb, DC, n0, c * 64, tid);
        CP_COMMIT();
    }
#pragma unroll
    for (int c = 0; c < 4; c++) {
        if (c + 2 < 4) {
            const int nb = (c + 2) % 3;
            loadS(sbase + nb * TILE_B, Ab, LDS_, m0, (c + 2) * 64, tid);
            loadS(sbase + (3 + nb) * TILE_B, Bb, DC, n0, (c + 2) * 64, tid);
        }
        CP_COMMIT();
        CP_WAITN(2);
        __syncthreads();
        chunk_mma(sbase + (c % 3) * TILE_B, sbase + (3 + c % 3) * TILE_B,
                  lane, wm, wn, acc);
        __syncthreads();
    }

#pragma unroll
    for (int mt = 0; mt < 2; mt++) {
#pragma unroll
        for (int half = 0; half < 2; half++) {
            const int row = m0 + wm + mt * 16 + g + half * 8;
            const float wc = g_wcol[b][row];
#pragma unroll
            for (int nt = 0; nt < 8; nt++) {
                const int col = n0 + wn + nt * 8 + tg * 2;
                const float v0 = acc[mt][nt][half * 2 + 0] + wc * hrow[col];
                const float v1 = acc[mt][nt][half * 2 + 1] + wc * hrow[col + 1];
                const size_t idx = (size_t)row * NCOL + col;
                Ob[idx] = Hb[idx] + v0 * INV_N;
                Ob[idx + 1] = Hb[idx + 1] + v1 * INV_N;
            }
        }
    }
}

// ---------------------------------------------------------------------------
// out borders: row 256 (all t) and col 2048 (d<256). grid (10,16), block 256.
// ---------------------------------------------------------------------------
__global__ void k_outb(const float* __restrict__ H, float* __restrict__ out) {
    const int b = blockIdx.y;
    const float* Hb = H + (size_t)b * HB;
    float* Ob = out + (size_t)b * HB;
    __shared__ float w[RDIM];
    __shared__ float hc[RDIM];
    const int tid = threadIdx.x;

    if (blockIdx.x < 9) {
        // row 256: out[256][t] = H[256][t] + sum_e W[256][e] H[e][t] / n
        if (tid < RDIM)
            w[tid] = __half2float(g_W[b][(size_t)256 * LDS_ + tid]);
        if (tid == 0)
            w[256] = __half2float(g_W[b][(size_t)256 * LDS_ + 256]);
        __syncthreads();
        const int t = blockIdx.x * 256 + tid;
        if (t < NCOL) {
            float s = 0.0f;
            for (int e = 0; e < RDIM; e++)
                s = fmaf(w[e], Hb[(size_t)e * NCOL + t], s);
            const size_t idx = (size_t)256 * NCOL + t;
            Ob[idx] = Hb[idx] + s * INV_N;
        }
    } else {
        // col 2048: out[d][2048] = H[d][2048] + sum_e W[d][e] hc[e] / n, d<256
        if (tid < RDIM) hc[tid] = g_hc[b][tid];
        if (tid == 0) hc[256] = g_hc[b][256];
        __syncthreads();
        const int d = tid;
        const __half* Wr = &g_W[b][(size_t)d * LDS_];
        float s = 0.0f;
        for (int e = 0; e < RDIM; e++)
            s = fmaf(__half2float(Wr[e]), hc[e], s);
        const size_t idx = (size_t)d * NCOL + 2048;
        Ob[idx] = Hb[idx] + s * INV_N;
    }
}

// ---------------------------------------------------------------------------
// setup: z<16 -> Hc/Htc core transpose; z==16 -> Pp/Qt; z==17 -> uv + hc.
// grid (32,12,18), block 256.
// ---------------------------------------------------------------------------
__global__ void k_setup(const float* __restrict__ H, const float* __restrict__ P,
                        const float* __restrict__ Q) {
    __shared__ float t[32][65];
    const int tid = threadIdx.x;
    const int z = blockIdx.z;

    if (z < NBAT) {
        if (blockIdx.y >= 8) return;
        const int b = z;
        const int c0 = blockIdx.x * 64;   // t
        const int r0 = blockIdx.y * 32;   // d
        const float* Hb = H + (size_t)b * HB;
        const int tx = tid & 31, ty = tid >> 5;
#pragma unroll
        for (int i = 0; i < 4; i++) {
            const int r = r0 + ty + i * 8;
            const int c = c0 + 2 * tx;
            const float v0 = Hb[(size_t)r * NCOL + c];
            const float v1 = Hb[(size_t)r * NCOL + c + 1];
            t[ty + i * 8][2 * tx] = v0;
            t[ty + i * 8][2 * tx + 1] = v1;
            *(__half2*)&g_Hc[b][(size_t)r * TC + c] = __floats2half2_rn(v0, v1);
        }
        __syncthreads();
#pragma unroll
        for (int i = 0; i < 4; i++) {
            const int cl = tid >> 2;
            const int pr = (tid & 3) + 4 * i;
            const float v0 = t[2 * pr][cl];
            const float v1 = t[2 * pr + 1][cl];
            *(__half2*)&g_Htc[b][(size_t)(c0 + cl) * DC + r0 + 2 * pr] =
                __floats2half2_rn(v0, v1);
        }
    } else if (z == NBAT) {
        if (blockIdx.x >= 12) return;
        const int c0 = blockIdx.x * 32, r0 = blockIdx.y * 32;
        const int tx = tid & 31, ty = tid >> 5;
#pragma unroll
        for (int i = 0; i < 4; i++) {
            const int r = r0 + ty + i * 8, c = c0 + tx;
            const bool in = (r < RDIM && c < RDIM);
            g_Pp[(size_t)r * LDS_ + c] =
                __float2half_rn(in ? P[(size_t)r * RDIM + c] : 0.0f);
            t[ty + i * 8][tx] = in ? Q[(size_t)r * RDIM + c] : 0.0f;
        }
        __syncthreads();
#pragma unroll
        for (int i = 0; i < 4; i++) {
            const int c = c0 + ty + i * 8, r = r0 + tx;
            g_Qt[(size_t)c * LDS_ + r] = __float2half_rn(t[tx][ty + i * 8]);
        }
    } else {
        if (blockIdx.x >= NBAT || blockIdx.y != 0) return;
        const int b = blockIdx.x;
        const float* Hb = H + (size_t)b * HB;
        __shared__ float hn[RDIM];
        for (int e = tid; e < RDIM; e += 256)
            hn[e] = Hb[(size_t)e * NCOL + (NCOL - 1)];
        __syncthreads();
        for (int i = tid; i < RDIM; i += 256) {
            float su = 0.0f, sv = 0.0f;
            for (int e = 0; e < RDIM; e++) {
                su += P[(size_t)i * RDIM + e] * hn[e];
                sv += hn[e] * Q[(size_t)e * RDIM + i];
            }
            g_u[b][i] = su;
            g_v[b][i] = sv;
        }
        // hc[d] = H[d][2048]  (== hn; reuse smem values)
        for (int d = tid; d < RDIM; d += 256) g_hc[b][d] = hn[d];
    }
}

// ---------------------------------------------------------------------------
extern "C" void kernel_launch(void* const* d_in, const int* in_sizes, int n_in,
                              void* d_out, int out_size) {
    const float* H = (const float*)d_in[0];
    const float* P = (const float*)d_in[1];
    const float* Q = (const float*)d_in[2];
    float* out = (float*)d_out;

    cudaFuncSetAttribute(k_syrk, cudaFuncAttributeMaxDynamicSharedMemorySize,
                         SMEM_GEMM);
    cudaFuncSetAttribute(k_ld<1>, cudaFuncAttributeMaxDynamicSharedMemorySize,
                         SMEM_GEMM);
    cudaFuncSetAttribute(k_ld<2>, cudaFuncAttributeMaxDynamicSharedMemorySize,
                         SMEM_GEMM);
    cudaFuncSetAttribute(k_outc, cudaFuncAttributeMaxDynamicSharedMemorySize,
                         SMEM_GEMM);

    __half *Pp, *Qt, *Gm, *Tm, *Wm;
    cudaGetSymbolAddress((void**)&Pp, g_Pp);
    cudaGetSymbolAddress((void**)&Qt, g_Qt);
    cudaGetSymbolAddress((void**)&Gm, g_G);
    cudaGetSymbolAddress((void**)&Tm, g_Tt);
    cudaGetSymbolAddress((void**)&Wm, g_W);

    // 1) setup: Hc/Htc core, Pp/Qt, u/v, hc
    k_setup<<<dim3(32, 12, NBAT + 2), 256>>>(H, P, Q);
    // 2) syrk core partials (3 sym tiles, split-K x3)
    k_syrk<<<dim3(3, 1, NBAT * 3), 256, SMEM_GEMM>>>();
    // 3) G core = sum partials + hc hc^T -> fp16 padded
    k_gred<<<dim3(64, NBAT), 256>>>();
    // 4) G borders (fp32 dots from H)
    k_gb<<<dim3(33, NBAT), 256>>>(H);
    // 5) T' = Qt (x) G
    k_ld<1><<<dim3(3, 3, NBAT), 256, SMEM_GEMM>>>(Qt, 0, Gm, GB_, Tm, GB_);
    // 6) W = Pp (x) T' - u v^T (+ wcol)
    k_ld<2><<<dim3(3, 3, NBAT), 256, SMEM_GEMM>>>(Pp, 0, Tm, GB_, Wm, GB_);
    // 7) out core
    k_outc<<<dim3(16, 2, NBAT), 256, SMEM_GEMM>>>(H, out);
    // 8) out borders
    k_outb<<<dim3(10, NBAT), 256>>>(H, out);
}

// round 11
// speedup vs baseline: 1.1744x; 1.1744x over previous
#include <cuda_runtime.h>
#include <cuda_fp16.h>
#include <cstdint>

// LinearSelfAttention via fp16-in/fp32-acc mma.sync (m16n8k16) + ldmatrix.
// out = H + ((P G Q - u v^T) H) / n,  G = H H^T, u = P h_n, v = Q^T h_n.
// Chain (all NT: C[m,n] = sum_k A[m,k] B[n,k]):
//   G  = Hp (x) Hp    symmetric 6 tiles + mirror, single pass, fp16 out
//   T' = Qt (x) G     ( = (G Q)^T )
//   W  = Pp (x) T' - u v^T
//   out= H + (W (x) Ht)/n
// 5 launches total. GEMM smem tiles: 128 rows x 64 halfs (128 B), XOR
// swizzle (c ^ (r&7)), fragments via ldmatrix.x4 (conflict-free).

#define RDIM 257
#define NCOL 2049
#define NBAT 16
#define INV_N (1.0f / 2048.0f)

#define MP   384
#define KHP  2176          // Hp/Ht t-extent (17*128, for out-stage tiles)
#define NCH  33            // syrk K chunks: 33*64 = 2112 >= 2049
#define LDS_ 384
#define GB_  ((size_t)LDS_ * LDS_)
#define HB   ((size_t)RDIM * NCOL)

__device__ __half g_Hp[NBAT][MP * KHP];    // padded H (zero-filled pads)
__device__ __half g_Ht[NBAT][KHP * MP];    // padded H^T
__device__ __half g_Pp[LDS_ * LDS_];
__device__ __half g_Qt[LDS_ * LDS_];
__device__ __half g_G[NBAT][LDS_ * LDS_];
__device__ __half g_Tt[NBAT][LDS_ * LDS_];
__device__ __half g_W[NBAT][LDS_ * LDS_];
__device__ float  g_u[NBAT][LDS_];         // pads stay 0 (static zero-init)
__device__ float  g_v[NBAT][LDS_];

// ---------------------------------------------------------------------------
__device__ __forceinline__ uint32_t smem_u32(const void* p) {
    uint32_t a;
    asm("{ .reg .u64 t; cvta.to.shared.u64 t, %1; cvt.u32.u64 %0, t; }"
        : "=r"(a) : "l"(p));
    return a;
}
__device__ __forceinline__ void cp16a(uint32_t sa, const void* g) {
    asm volatile("cp.async.cg.shared.global [%0], [%1], 16;"
                 :: "r"(sa), "l"(g) : "memory");
}
#define CP_COMMIT() asm volatile("cp.async.commit_group;" ::: "memory")
#define CP_WAITN(n) asm volatile("cp.async.wait_group %0;" :: "n"(n) : "memory")

__device__ __forceinline__ void mma8(float* c, const uint32_t* a,
                                     const uint32_t* b) {
    asm volatile(
        "mma.sync.aligned.m16n8k16.row.col.f32.f16.f16.f32 "
        "{%0,%1,%2,%3}, {%4,%5,%6,%7}, {%8,%9}, {%0,%1,%2,%3};"
        : "+f"(c[0]), "+f"(c[1]), "+f"(c[2]), "+f"(c[3])
        : "r"(a[0]), "r"(a[1]), "r"(a[2]), "r"(a[3]), "r"(b[0]), "r"(b[1]));
}
__device__ __forceinline__ void ldsm4(uint32_t* r, uint32_t a) {
    asm volatile(
        "ldmatrix.sync.aligned.m8n8.x4.shared.b16 {%0,%1,%2,%3}, [%4];"
        : "=r"(r[0]), "=r"(r[1]), "=r"(r[2]), "=r"(r[3]) : "r"(a));
}

// Swizzled tile load: 128 rows x 64 halfs (128 B/row), chunk c at (c^(r&7)).
#define TILE_B 16384
#define SMEM_GEMM (6 * TILE_B)

__device__ __forceinline__ void loadS(uint32_t sbase, const __half* __restrict__ g,
                                      int ld, int r0, int k0, int tid) {
    const int chunk = tid & 7;
    const int rb = tid >> 3;
    const __half* gp = g + (size_t)r0 * ld + k0 + chunk * 8;
#pragma unroll
    for (int i = 0; i < 4; i++) {
        const int r = rb + i * 32;
        const uint32_t off = (uint32_t)(r * 128 + ((chunk ^ (r & 7)) << 4));
        cp16a(sbase + off, gp + (size_t)r * ld);
    }
}

__device__ __forceinline__ void chunk_mma(uint32_t Ab, uint32_t Bb, int lane,
                                          int wm, int wn, float (&acc)[2][8][4]) {
    const int rA = lane & 15;
    const int hi = lane >> 4;
#pragma unroll
    for (int ks = 0; ks < 4; ks++) {
        uint32_t a[2][4], bt[4][4];
#pragma unroll
        for (int mt = 0; mt < 2; mt++) {
            const int row = wm + mt * 16 + rA;
            ldsm4(a[mt], Ab + row * 128 + (((ks * 2 + hi) ^ (row & 7)) << 4));
        }
#pragma unroll
        for (int n2 = 0; n2 < 4; n2++) {
            const int row = wn + n2 * 16 + rA;
            ldsm4(bt[n2], Bb + row * 128 + (((ks * 2 + hi) ^ (row & 7)) << 4));
        }
#pragma unroll
        for (int mt = 0; mt < 2; mt++)
#pragma unroll
            for (int n2 = 0; n2 < 4; n2++) {
                uint32_t b0[2] = {bt[n2][0], bt[n2][2]};
                uint32_t b1[2] = {bt[n2][1], bt[n2][3]};
                mma8(acc[mt][2 * n2 + 0], a[mt], b0);
                mma8(acc[mt][2 * n2 + 1], a[mt], b1);
            }
    }
}

#define DECL_FRAG() \
    float acc[2][8][4]; \
    _Pragma("unroll") for (int i = 0; i < 2; i++) \
    _Pragma("unroll") for (int j = 0; j < 8; j++) \
    _Pragma("unroll") for (int r = 0; r < 4; r++) acc[i][j][r] = 0.0f;

// ---------------------------------------------------------------------------
// syrk: G = Hp (x) Hp, 6 symmetric tiles, full K (33 chunks), fp16 out.
// grid (6,1,16), 96 KB smem, depth-3 pipeline.
// ---------------------------------------------------------------------------
__global__ void __launch_bounds__(256, 2) k_syrk() {
    extern __shared__ __half sm[];
    const uint32_t sbase = smem_u32(sm);
    const int tid = threadIdx.x;
    const int b = blockIdx.z;
    const int TI[6] = {0, 0, 0, 1, 1, 2};
    const int TJ[6] = {0, 1, 2, 1, 2, 2};
    const int ti = TI[blockIdx.x], tj = TJ[blockIdx.x];
    const int m0 = ti * 128, n0 = tj * 128;

    const __half* Hb = g_Hp[b];
    __half* Gb = g_G[b];

    const int lane = tid & 31, wid = tid >> 5;
    const int wm = (wid & 3) * 32;
    const int wn = (wid >> 2) * 64;
    const int g = lane >> 2, tg = lane & 3;

    DECL_FRAG();

#pragma unroll
    for (int c = 0; c < 2; c++) {
        loadS(sbase + c * TILE_B, Hb, KHP, m0, c * 64, tid);
        loadS(sbase + (3 + c) * TILE_B, Hb, KHP, n0, c * 64, tid);
        CP_COMMIT();
    }
    for (int c = 0; c < NCH; c++) {
        if (c + 2 < NCH) {
            const int nb = (c + 2) % 3;
            const int k0 = (c + 2) * 64;
            loadS(sbase + nb * TILE_B, Hb, KHP, m0, k0, tid);
            loadS(sbase + (3 + nb) * TILE_B, Hb, KHP, n0, k0, tid);
        }
        CP_COMMIT();
        CP_WAITN(2);
        __syncthreads();
        chunk_mma(sbase + (c % 3) * TILE_B, sbase + (3 + c % 3) * TILE_B,
                  lane, wm, wn, acc);
        __syncthreads();
    }

    // epilogue: fp16 own tile + mirror for off-diagonal
#pragma unroll
    for (int mt = 0; mt < 2; mt++) {
#pragma unroll
        for (int half = 0; half < 2; half++) {
            const int row = m0 + wm + mt * 16 + g + half * 8;
#pragma unroll
            for (int nt = 0; nt < 8; nt++) {
                const int col = n0 + wn + nt * 8 + tg * 2;
                const float v0 = acc[mt][nt][half * 2 + 0];
                const float v1 = acc[mt][nt][half * 2 + 1];
                *(__half2*)&Gb[(size_t)row * LDS_ + col] =
                    __floats2half2_rn(v0, v1);
                if (ti != tj) {
                    Gb[(size_t)col * LDS_ + row] = __float2half_rn(v0);
                    Gb[(size_t)(col + 1) * LDS_ + row] = __float2half_rn(v1);
                }
            }
        }
    }
}

// ---------------------------------------------------------------------------
// K=320 stages (5 chunks of 64), depth-3, 2 CTAs/SM:
//  MODE 1: T' = Qt (x) G          -> fp16 padded
//  MODE 2: W  = Pp (x) T' - uv^T  -> fp16 padded
//  MODE 3: out= H + acc/n         -> fp32 guarded (ldc = NCOL)
// ---------------------------------------------------------------------------
template <int MODE>
__global__ void __launch_bounds__(256, 2)
k_ld(const __half* __restrict__ A, size_t sA, int lda,
     const __half* __restrict__ B, size_t sB, int ldb,
     void* __restrict__ Cv, size_t sC, int ldc,
     const float* __restrict__ E) {
    extern __shared__ __half sm[];
    const uint32_t sbase = smem_u32(sm);
    const int tid = threadIdx.x;
    const int b = blockIdx.z;
    const int m0 = blockIdx.y * 128, n0 = blockIdx.x * 128;
    const __half* Ab = A + (size_t)b * sA;
    const __half* Bb = B + (size_t)b * sB;

    const int lane = tid & 31, wid = tid >> 5;
    const int wm = (wid & 3) * 32;
    const int wn = (wid >> 2) * 64;
    const int g = lane >> 2, tg = lane & 3;

    DECL_FRAG();

#pragma unroll
    for (int c = 0; c < 2; c++) {
        loadS(sbase + c * TILE_B, Ab, lda, m0, c * 64, tid);
        loadS(sbase + (3 + c) * TILE_B, Bb, ldb, n0, c * 64, tid);
        CP_COMMIT();
    }
#pragma unroll
    for (int c = 0; c < 5; c++) {
        if (c + 2 < 5) {
            const int nb = (c + 2) % 3;
            loadS(sbase + nb * TILE_B, Ab, lda, m0, (c + 2) * 64, tid);
            loadS(sbase + (3 + nb) * TILE_B, Bb, ldb, n0, (c + 2) * 64, tid);
        }
        CP_COMMIT();
        CP_WAITN(2);
        __syncthreads();
        chunk_mma(sbase + (c % 3) * TILE_B, sbase + (3 + c % 3) * TILE_B,
                  lane, wm, wn, acc);
        __syncthreads();
    }

#pragma unroll
    for (int mt = 0; mt < 2; mt++) {
#pragma unroll
        for (int half = 0; half < 2; half++) {
            const int row = m0 + wm + mt * 16 + g + half * 8;
            if (MODE == 3 && row >= RDIM) continue;
            float uu = 0.0f;
            if (MODE == 2) uu = g_u[b][row];
#pragma unroll
            for (int nt = 0; nt < 8; nt++) {
                const int col = n0 + wn + nt * 8 + tg * 2;
                float v0 = acc[mt][nt][half * 2 + 0];
                float v1 = acc[mt][nt][half * 2 + 1];
                if (MODE == 1) {
                    __half* Ch = (__half*)Cv + (size_t)b * sC;
                    *(__half2*)&Ch[(size_t)row * ldc + col] =
                        __floats2half2_rn(v0, v1);
                } else if (MODE == 2) {
                    __half* Ch = (__half*)Cv + (size_t)b * sC;
                    v0 -= uu * g_v[b][col];
                    v1 -= uu * g_v[b][col + 1];
                    *(__half2*)&Ch[(size_t)row * ldc + col] =
                        __floats2half2_rn(v0, v1);
                } else {
                    float* Cf = (float*)Cv + (size_t)b * sC;
                    const float* Eb = E + (size_t)b * sC;
                    const size_t idx = (size_t)row * ldc + col;
                    if (col < NCOL) Cf[idx] = Eb[idx] + v0 * INV_N;
                    if (col + 1 < NCOL) Cf[idx + 1] = Eb[idx + 1] + v1 * INV_N;
                }
            }
        }
    }
}

// ---------------------------------------------------------------------------
// fused setup: z<16 padH(batch z) -> Hp/Ht; z==16 padPQ; z==17 uv.
// grid (34, 12, 18), block 256. Ht stores: 16B per thread, 64B-packed rows.
// ---------------------------------------------------------------------------
__global__ void k_setup(const float* __restrict__ H, const float* __restrict__ P,
                        const float* __restrict__ Q) {
    __shared__ float t[32][65];
    const int tid = threadIdx.x;
    const int z = blockIdx.z;

    if (z < NBAT) {
        const int b = z;
        const int c0 = blockIdx.x * 64;   // t
        const int r0 = blockIdx.y * 32;   // d
        const float* Hb = H + (size_t)b * HB;
        const int tx = tid & 31, ty = tid >> 5;
#pragma unroll
        for (int i = 0; i < 4; i++) {
            const int r = r0 + ty + i * 8;
            const int c = c0 + 2 * tx;
            float v0 = 0.0f, v1 = 0.0f;
            if (r < RDIM) {
                if (c < NCOL) v0 = Hb[(size_t)r * NCOL + c];
                if (c + 1 < NCOL) v1 = Hb[(size_t)r * NCOL + c + 1];
            }
            t[ty + i * 8][2 * tx] = v0;
            t[ty + i * 8][2 * tx + 1] = v1;
            *(__half2*)&g_Hp[b][(size_t)r * KHP + c] = __floats2half2_rn(v0, v1);
        }
        __syncthreads();
        // Ht: thread -> (t-row = c0 + tid/4, d-cols = (tid&3)*8 .. +7), 16B store
        {
            const int tr = tid >> 2;
            const int dq = (tid & 3) * 8;
            uint4 pack;
            __half2* ph = (__half2*)&pack;
#pragma unroll
            for (int k = 0; k < 4; k++)
                ph[k] = __floats2half2_rn(t[dq + 2 * k][tr], t[dq + 2 * k + 1][tr]);
            *(uint4*)&g_Ht[b][(size_t)(c0 + tr) * MP + r0 + dq] = pack;
        }
    } else if (z == NBAT) {
        if (blockIdx.x >= 12) return;
        const int c0 = blockIdx.x * 32, r0 = blockIdx.y * 32;
        const int tx = tid & 31, ty = tid >> 5;
#pragma unroll
        for (int i = 0; i < 4; i++) {
            const int r = r0 + ty + i * 8, c = c0 + tx;
            const bool in = (r < RDIM && c < RDIM);
            g_Pp[(size_t)r * LDS_ + c] =
                __float2half_rn(in ? P[(size_t)r * RDIM + c] : 0.0f);
            t[ty + i * 8][tx] = in ? Q[(size_t)r * RDIM + c] : 0.0f;
        }
        __syncthreads();
#pragma unroll
        for (int i = 0; i < 4; i++) {
            const int c = c0 + ty + i * 8, r = r0 + tx;
            g_Qt[(size_t)c * LDS_ + r] = __float2half_rn(t[tx][ty + i * 8]);
        }
    } else {
        if (blockIdx.x >= NBAT || blockIdx.y != 0) return;
        const int b = blockIdx.x;
        const float* Hb = H + (size_t)b * HB;
        __shared__ float hn[RDIM];
        for (int e = tid; e < RDIM; e += 256)
            hn[e] = Hb[(size_t)e * NCOL + (NCOL - 1)];
        __syncthreads();
        for (int i = tid; i < RDIM; i += 256) {
            float su = 0.0f, sv = 0.0f;
            for (int e = 0; e < RDIM; e++) {
                su += P[(size_t)i * RDIM + e] * hn[e];
                sv += hn[e] * Q[(size_t)e * RDIM + i];
            }
            g_u[b][i] = su;
            g_v[b][i] = sv;
        }
    }
}

// ---------------------------------------------------------------------------
extern "C" void kernel_launch(void* const* d_in, const int* in_sizes, int n_in,
                              void* d_out, int out_size) {
    const float* H = (const float*)d_in[0];
    const float* P = (const float*)d_in[1];
    const float* Q = (const float*)d_in[2];
    float* out = (float*)d_out;

    cudaFuncSetAttribute(k_syrk, cudaFuncAttributeMaxDynamicSharedMemorySize,
                         SMEM_GEMM);
    cudaFuncSetAttribute(k_ld<1>, cudaFuncAttributeMaxDynamicSharedMemorySize,
                         SMEM_GEMM);
    cudaFuncSetAttribute(k_ld<2>, cudaFuncAttributeMaxDynamicSharedMemorySize,
                         SMEM_GEMM);
    cudaFuncSetAttribute(k_ld<3>, cudaFuncAttributeMaxDynamicSharedMemorySize,
                         SMEM_GEMM);

    __half *Pp, *Qt, *Gm, *Tm, *Wm, *Ht;
    cudaGetSymbolAddress((void**)&Pp, g_Pp);
    cudaGetSymbolAddress((void**)&Qt, g_Qt);
    cudaGetSymbolAddress((void**)&Gm, g_G);
    cudaGetSymbolAddress((void**)&Tm, g_Tt);
    cudaGetSymbolAddress((void**)&Wm, g_W);
    cudaGetSymbolAddress((void**)&Ht, g_Ht);

    // 1) setup: Hp/Ht, Pp/Qt, u/v
    k_setup<<<dim3(34, 12, NBAT + 2), 256>>>(H, P, Q);
    // 2) G = Hp (x) Hp (6 symmetric tiles, full K, fp16 out)
    k_syrk<<<dim3(6, 1, NBAT), 256, SMEM_GEMM>>>();
    // 3) T' = Qt (x) G
    k_ld<1><<<dim3(3, 3, NBAT), 256, SMEM_GEMM>>>(
        Qt, 0, LDS_, Gm, GB_, LDS_, Tm, GB_, LDS_, nullptr);
    // 4) W = Pp (x) T' - u v^T
    k_ld<2><<<dim3(3, 3, NBAT), 256, SMEM_GEMM>>>(
        Pp, 0, LDS_, Tm, GB_, LDS_, Wm, GB_, LDS_, nullptr);
    // 5) out = H + (W (x) Ht)/n
    k_ld<3><<<dim3(17, 3, NBAT), 256, SMEM_GEMM>>>(
        Wm, GB_, LDS_, Ht, (size_t)KHP * MP, MP, out, HB, NCOL, H);
}